// round 5
// baseline (speedup 1.0000x reference)
#include <cuda_runtime.h>
#include <cstdint>

// SMPL forward kinematics, algebraically reduced:
//   out[b,0]   = 0
//   out[b,c,m] = out[b,par(c),m] + sum_l R[b,par(c)][m][l] * v_c[l]
// where v_c = (off[c,1], off[c,2], off[c,0]) -- the G-permutations cancel.
//
// R5: 16 warps/SM (256-thr blocks x 2/SM), warp-autonomous 8-body tiles,
// depth-1 cp.async prefetch (double buffer). Latency hiding comes from
// warp count, not pipeline depth (R4 showed depth alone regresses).
// Input staged at stride 55 float4/body (conflict-free LDS.128); output
// staged at stride 19 then streamed fully coalesced. Dead leaf-matrix
// entries {9,10,18,19,52,53} never loaded.

#define TB 8                        // bodies per tile
#define STRIDE 55                   // float4 per body in smem
#define BUFQ (TB * STRIDE)          // 440 float4 per buffer
#define WPB 8                       // warps per block

static __device__ __forceinline__ void cp16(void* smem_dst, const void* gsrc) {
    unsigned s = (unsigned)__cvta_generic_to_shared(smem_dst);
    asm volatile("cp.async.cg.shared.global [%0], [%1], 16;\n" :: "r"(s), "l"(gsrc));
}

#define LOADA(e0) do {                                          \
    float4 q0 = my[(e0)]; float4 q1 = my[(e0)+1]; float4 q2 = my[(e0)+2]; \
    A[0]=q0.x; A[1]=q0.y; A[2]=q0.z;  A[3]=q0.w;                \
    A[4]=q1.x; A[5]=q1.y; A[6]=q1.z;  A[7]=q1.w;                \
    A[8]=q2.x; A[9]=q2.y; A[10]=q2.z; A[11]=q2.w;               \
} while(0)

#define CH(c, p, r, vx, vy, vz) do {                                              \
    px[c] = fmaf(A[(r)+2],(vz), fmaf(A[(r)+1],(vy), fmaf(A[(r)+0],(vx), px[p]))); \
    py[c] = fmaf(A[(r)+5],(vz), fmaf(A[(r)+4],(vy), fmaf(A[(r)+3],(vx), py[p]))); \
    pz[c] = fmaf(A[(r)+8],(vz), fmaf(A[(r)+7],(vy), fmaf(A[(r)+6],(vx), pz[p]))); \
} while(0)

// Stage 4 joints (j..j+3) = 3 float4 at staging slots k0..k0+2
#define ST4(k0, j) do {                                                        \
    stg[(k0)+0] = make_float4(px[(j)+0], py[(j)+0], pz[(j)+0], px[(j)+1]);     \
    stg[(k0)+1] = make_float4(py[(j)+1], pz[(j)+1], px[(j)+2], py[(j)+2]);     \
    stg[(k0)+2] = make_float4(pz[(j)+2], px[(j)+3], py[(j)+3], pz[(j)+3]);     \
} while(0)

__global__ void __launch_bounds__(256, 2)
smpl_fk_kernel(const float4* __restrict__ in4, float4* __restrict__ out4, int nb) {
    extern __shared__ float4 sm[];
    const int lane = threadIdx.x & 31;
    const int warp = threadIdx.x >> 5;
    float4* const buf0 = sm + warp * (2 * BUFQ);
    float4* const buf1 = buf0 + BUFQ;

    const int nT = (nb + TB - 1) / TB;
    const int ws = gridDim.x * WPB;
    int t = blockIdx.x * WPB + warp;
    if (t >= nT) return;

    // Dead entries {9,10,18,19,52,53} (leaf-joint matrices) never loaded.
    const bool do1 = !(lane == 9 || lane == 10 || lane == 18 || lane == 19);
    const bool do2 = (lane < 20);

    auto load_tile = [&](int tt, float4* buf) {
        const long long b0 = (long long)tt * TB;
        const float4* src = in4 + b0 * 54;
        const int nbl = (int)min((long long)TB, (long long)nb - b0);
        if (nbl == TB) {
            #pragma unroll
            for (int bl = 0; bl < TB; bl++) {
                if (do1) cp16(&buf[bl*STRIDE + lane],      &src[bl*54 + lane]);
                if (do2) cp16(&buf[bl*STRIDE + lane + 32], &src[bl*54 + lane + 32]);
            }
        } else {
            for (int bl = 0; bl < nbl; bl++) {
                if (do1) cp16(&buf[bl*STRIDE + lane],      &src[bl*54 + lane]);
                if (do2) cp16(&buf[bl*STRIDE + lane + 32], &src[bl*54 + lane + 32]);
            }
        }
        asm volatile("cp.async.commit_group;\n" ::: "memory");
    };

    load_tile(t, buf0);                    // prologue
    int cur = 0;

    while (true) {
        const int tn = t + ws;
        float4* const cbuf = cur ? buf1 : buf0;
        if (tn < nT) {
            load_tile(tn, cur ? buf0 : buf1);                    // prefetch
            asm volatile("cp.async.wait_group 1;\n" ::: "memory");
        } else {
            asm volatile("cp.async.wait_group 0;\n" ::: "memory");
        }
        __syncwarp();

        const long long b0 = (long long)t * TB;
        const int nbl = (int)min((long long)TB, (long long)nb - b0);
        const bool active = (lane < nbl);

        if (active) {
            const float4* my = cbuf + lane * STRIDE;
            float A[12];
            float px[24], py[24], pz[24];
            px[0] = 0.f; py[0] = 0.f; pz[0] = 0.f;

            LOADA(0);                                   // j=0  (r=0)
            CH(1, 0, 0,  0.0372f, -0.0522f, -0.0112f);
            CH(5, 0, 0, -0.0383f, -0.0575f, -0.0086f);
            CH(9, 0, 0,  0.0028f,  0.0790f, -0.0244f);
            LOADA(2);                                   // j=1  (r=1)
            CH(2, 1, 1,  0.0276f, -0.2453f,  0.0051f);
            LOADA(4);                                   // j=2  (r=2)
            CH(3, 2, 2, -0.0094f, -0.2710f, -0.0238f);
            LOADA(6);                                   // j=3  (r=3)
            CH(4, 3, 3,  0.0261f, -0.0383f,  0.0775f);
            LOADA(11);                                  // j=5  (r=1)
            CH(6, 5, 1, -0.0275f, -0.2436f, -0.0031f);
            LOADA(13);                                  // j=6  (r=2)
            CH(7, 6, 2,  0.0121f, -0.2666f, -0.0219f);
            LOADA(15);                                  // j=7  (r=3)
            CH(8, 7, 3, -0.0221f, -0.0394f,  0.0827f);
            LOADA(20);                                  // j=9  (r=1)
            CH(10, 9, 1,  0.0028f,  0.0876f,  0.0170f);
            LOADA(22);                                  // j=10 (r=2)
            CH(11, 10, 2, -0.0014f,  0.0356f,  0.0018f);
            LOADA(24);                                  // j=11 (r=3)
            CH(12, 11, 3, -0.0085f,  0.1343f, -0.0212f);
            CH(14, 11, 3,  0.0455f,  0.0724f, -0.0120f);
            CH(19, 11, 3, -0.0527f,  0.0714f, -0.0150f);
            LOADA(27);                                  // j=12 (r=0)
            CH(13, 12, 0,  0.0064f,  0.0565f,  0.0320f);
            LOADA(31);                                  // j=14 (r=2)
            CH(15, 14, 2,  0.0780f,  0.0287f, -0.0121f);
            LOADA(33);                                  // j=15 (r=3)
            CH(16, 15, 3,  0.1621f, -0.0099f, -0.0146f);
            LOADA(36);                                  // j=16 (r=0)
            CH(17, 16, 0,  0.1687f,  0.0081f, -0.0047f);
            LOADA(38);                                  // j=17 (r=1)
            CH(18, 17, 1,  0.0550f, -0.0068f, -0.0099f);
            LOADA(42);                                  // j=19 (r=3)
            CH(20, 19, 3, -0.0719f,  0.0297f, -0.0054f);
            LOADA(45);                                  // j=20 (r=0)
            CH(21, 20, 0, -0.1651f, -0.0091f, -0.0198f);
            LOADA(47);                                  // j=21 (r=1)
            CH(22, 21, 1, -0.1708f,  0.0043f, -0.0038f);
            LOADA(49);                                  // j=22 (r=2)
            CH(23, 22, 2, -0.0563f, -0.0055f, -0.0064f);

            __syncwarp();                   // compute reads of cbuf done (all lanes)
            float4* stg = cbuf + lane * 19; // stage at stride 19 (conflict-free)
            ST4(0,  0);  ST4(3,  4);  ST4(6,  8);
            ST4(9,  12); ST4(12, 16); ST4(15, 20);
        } else {
            __syncwarp();
        }
        __syncwarp();

        // ---- fully coalesced store stream: nbl*18 contiguous float4 ----
        float4* dstw = out4 + b0 * 18;
        const int lim = nbl * 18;           // <= 144
        #pragma unroll
        for (int k = 0; k < 5; k++) {
            int idx = k * 32 + lane;
            int bl  = idx / 18;
            int e   = idx - bl * 18;
            if (idx < lim) dstw[idx] = cbuf[bl * 19 + e];
        }
        __syncwarp();                       // stream reads done before cbuf reused

        if (tn >= nT) break;
        t = tn;
        cur ^= 1;
    }
}

extern "C" void kernel_launch(void* const* d_in, const int* in_sizes, int n_in,
                              void* d_out, int out_size) {
    const float4* in4 = (const float4*)d_in[0];   // orientations [B,24,3,3] f32
    float4* out4 = (float4*)d_out;                // [B,24,3] f32
    const int nb = in_sizes[0] / 216;             // B
    const int smem = WPB * 2 * BUFQ * 16;         // 112,640 B
    cudaFuncSetAttribute(smpl_fk_kernel, cudaFuncAttributeMaxDynamicSharedMemorySize, smem);
    const int nT = (nb + TB - 1) / TB;
    int blocks = 296;                              // 2 per SM (148 SMs)
    const int maxb = (nT + WPB - 1) / WPB;
    if (blocks > maxb) blocks = maxb;
    if (blocks < 1) blocks = 1;
    smpl_fk_kernel<<<blocks, 256, smem>>>(in4, out4, nb);
}

// round 6
// speedup vs baseline: 1.1195x; 1.1195x over previous
#include <cuda_runtime.h>
#include <cstdint>

// SMPL forward kinematics, algebraically reduced:
//   out[b,0]   = 0
//   out[b,c,m] = out[b,par(c),m] + sum_l R[b,par(c)][m][l] * v_c[l]
// where v_c = (off[c,1], off[c,2], off[c,0]) -- the G-permutations cancel.
//
// R6 = R3 (best: TB=16, 4 warps/block, 2 blocks/SM, double buffer) with the
// next-tile cp.async issue SPLIT INTO 4 CHUNKS interleaved between compute
// quarters, so each warp keeps DRAM requests in flight across ~70% of its
// iteration instead of one burst at the top. wait_group 0 at iteration top
// (only the current tile's chunks are pending there).
// Input staged at stride 55 float4/body (conflict-free LDS.128); output
// staged at stride 19 then streamed fully coalesced. Dead leaf-matrix
// entries {9,10,18,19,52,53} never loaded.

#define TB 16                       // bodies per tile
#define STRIDE 55                   // float4 per body in smem
#define BUFQ (TB * STRIDE)          // 880 float4 per buffer
#define WPB 4                       // warps per block

static __device__ __forceinline__ void cp16(void* smem_dst, const void* gsrc) {
    unsigned s = (unsigned)__cvta_generic_to_shared(smem_dst);
    asm volatile("cp.async.cg.shared.global [%0], [%1], 16;\n" :: "r"(s), "l"(gsrc));
}

#define LOADA(e0) do {                                          \
    float4 q0 = my[(e0)]; float4 q1 = my[(e0)+1]; float4 q2 = my[(e0)+2]; \
    A[0]=q0.x; A[1]=q0.y; A[2]=q0.z;  A[3]=q0.w;                \
    A[4]=q1.x; A[5]=q1.y; A[6]=q1.z;  A[7]=q1.w;                \
    A[8]=q2.x; A[9]=q2.y; A[10]=q2.z; A[11]=q2.w;               \
} while(0)

#define CH(c, p, r, vx, vy, vz) do {                                              \
    px[c] = fmaf(A[(r)+2],(vz), fmaf(A[(r)+1],(vy), fmaf(A[(r)+0],(vx), px[p]))); \
    py[c] = fmaf(A[(r)+5],(vz), fmaf(A[(r)+4],(vy), fmaf(A[(r)+3],(vx), py[p]))); \
    pz[c] = fmaf(A[(r)+8],(vz), fmaf(A[(r)+7],(vy), fmaf(A[(r)+6],(vx), pz[p]))); \
} while(0)

// Stage 4 joints (j..j+3) = 3 float4 at staging slots k0..k0+2
#define ST4(k0, j) do {                                                        \
    stg[(k0)+0] = make_float4(px[(j)+0], py[(j)+0], pz[(j)+0], px[(j)+1]);     \
    stg[(k0)+1] = make_float4(py[(j)+1], pz[(j)+1], px[(j)+2], py[(j)+2]);     \
    stg[(k0)+2] = make_float4(pz[(j)+2], px[(j)+3], py[(j)+3], pz[(j)+3]);     \
} while(0)

__global__ void __launch_bounds__(128, 2)
smpl_fk_kernel(const float4* __restrict__ in4, float4* __restrict__ out4, int nb) {
    extern __shared__ float4 sm[];
    const int lane = threadIdx.x & 31;
    const int warp = threadIdx.x >> 5;
    float4* const buf0 = sm + warp * (2 * BUFQ);
    float4* const buf1 = buf0 + BUFQ;

    const int nT = (nb + TB - 1) / TB;
    const int ws = gridDim.x * WPB;
    int t = blockIdx.x * WPB + warp;
    if (t >= nT) return;

    // Dead entries {9,10,18,19,52,53} (leaf-joint matrices) never loaded.
    const bool do1 = !(lane == 9 || lane == 10 || lane == 18 || lane == 19);
    const bool do2 = (lane < 20);

    // Load chunk c (bodies 4c..4c+3) of tile tt into buf, then commit.
    auto load_chunk = [&](int tt, float4* buf, int c) {
        const long long b0 = (long long)tt * TB;
        const float4* src = in4 + b0 * 54;
        const int nbl = (int)min((long long)TB, (long long)nb - b0);
        const int bl0 = c * 4;
        #pragma unroll
        for (int i = 0; i < 4; i++) {
            const int bl = bl0 + i;
            if (bl < nbl) {
                if (do1) cp16(&buf[bl*STRIDE + lane],      &src[bl*54 + lane]);
                if (do2) cp16(&buf[bl*STRIDE + lane + 32], &src[bl*54 + lane + 32]);
            }
        }
        asm volatile("cp.async.commit_group;\n" ::: "memory");
    };

    // ---- prologue: all 4 chunks of the first tile ----
    #pragma unroll
    for (int c = 0; c < 4; c++) load_chunk(t, buf0, c);

    int cur = 0;
    while (true) {
        const int tn = t + ws;
        float4* const cbuf = cur ? buf1 : buf0;
        float4* const nbuf = cur ? buf0 : buf1;

        // Only the current tile's chunks are pending here.
        asm volatile("cp.async.wait_group 0;\n" ::: "memory");
        __syncwarp();

        const long long b0 = (long long)t * TB;
        const int nbl = (int)min((long long)TB, (long long)nb - b0);
        const bool active = (lane < nbl);
        const bool pre = (tn < nT);

        const float4* my = cbuf + lane * STRIDE;
        float A[12];
        float px[24], py[24], pz[24];

        if (pre) load_chunk(tn, nbuf, 0);                // chunk 0 in flight ASAP

        if (active) {                                    // Q1: joints 0-3
            px[0] = 0.f; py[0] = 0.f; pz[0] = 0.f;
            LOADA(0);
            CH(1, 0, 0,  0.0372f, -0.0522f, -0.0112f);
            CH(5, 0, 0, -0.0383f, -0.0575f, -0.0086f);
            CH(9, 0, 0,  0.0028f,  0.0790f, -0.0244f);
            LOADA(2);
            CH(2, 1, 1,  0.0276f, -0.2453f,  0.0051f);
            LOADA(4);
            CH(3, 2, 2, -0.0094f, -0.2710f, -0.0238f);
            LOADA(6);
            CH(4, 3, 3,  0.0261f, -0.0383f,  0.0775f);
        }

        if (pre) load_chunk(tn, nbuf, 1);

        if (active) {                                    // Q2: joints 5-8
            LOADA(11);
            CH(6, 5, 1, -0.0275f, -0.2436f, -0.0031f);
            LOADA(13);
            CH(7, 6, 2,  0.0121f, -0.2666f, -0.0219f);
            LOADA(15);
            CH(8, 7, 3, -0.0221f, -0.0394f,  0.0827f);
        }

        if (pre) load_chunk(tn, nbuf, 2);

        if (active) {                                    // Q3: joints 9-13,14,19
            LOADA(20);
            CH(10, 9, 1,  0.0028f,  0.0876f,  0.0170f);
            LOADA(22);
            CH(11, 10, 2, -0.0014f,  0.0356f,  0.0018f);
            LOADA(24);
            CH(12, 11, 3, -0.0085f,  0.1343f, -0.0212f);
            CH(14, 11, 3,  0.0455f,  0.0724f, -0.0120f);
            CH(19, 11, 3, -0.0527f,  0.0714f, -0.0150f);
            LOADA(27);
            CH(13, 12, 0,  0.0064f,  0.0565f,  0.0320f);
        }

        if (pre) load_chunk(tn, nbuf, 3);

        if (active) {                                    // Q4: joints 15-18, 20-23
            LOADA(31);
            CH(15, 14, 2,  0.0780f,  0.0287f, -0.0121f);
            LOADA(33);
            CH(16, 15, 3,  0.1621f, -0.0099f, -0.0146f);
            LOADA(36);
            CH(17, 16, 0,  0.1687f,  0.0081f, -0.0047f);
            LOADA(38);
            CH(18, 17, 1,  0.0550f, -0.0068f, -0.0099f);
            LOADA(42);
            CH(20, 19, 3, -0.0719f,  0.0297f, -0.0054f);
            LOADA(45);
            CH(21, 20, 0, -0.1651f, -0.0091f, -0.0198f);
            LOADA(47);
            CH(22, 21, 1, -0.1708f,  0.0043f, -0.0038f);
            LOADA(49);
            CH(23, 22, 2, -0.0563f, -0.0055f, -0.0064f);
        }

        __syncwarp();                       // compute reads of cbuf done
        if (active) {                       // stage at stride 19 (conflict-free)
            float4* stg = cbuf + lane * 19;
            ST4(0,  0);  ST4(3,  4);  ST4(6,  8);
            ST4(9,  12); ST4(12, 16); ST4(15, 20);
        }
        __syncwarp();

        // ---- fully coalesced store stream: nbl*18 contiguous float4 ----
        float4* dstw = out4 + b0 * 18;
        const int lim = nbl * 18;           // <= 288
        #pragma unroll
        for (int k = 0; k < 9; k++) {
            int idx = k * 32 + lane;
            int bl  = idx / 18;
            int e   = idx - bl * 18;
            if (idx < lim) dstw[idx] = cbuf[bl * 19 + e];
        }
        __syncwarp();                       // stream reads done before cbuf reused

        if (!pre) break;
        t = tn;
        cur ^= 1;
    }
}

extern "C" void kernel_launch(void* const* d_in, const int* in_sizes, int n_in,
                              void* d_out, int out_size) {
    const float4* in4 = (const float4*)d_in[0];   // orientations [B,24,3,3] f32
    float4* out4 = (float4*)d_out;                // [B,24,3] f32
    const int nb = in_sizes[0] / 216;             // B
    const int smem = WPB * 2 * BUFQ * 16;         // 112,640 B
    cudaFuncSetAttribute(smpl_fk_kernel, cudaFuncAttributeMaxDynamicSharedMemorySize, smem);
    const int nT = (nb + TB - 1) / TB;
    int blocks = 296;                              // 2 per SM (148 SMs)
    const int maxb = (nT + WPB - 1) / WPB;
    if (blocks > maxb) blocks = maxb;
    if (blocks < 1) blocks = 1;
    smpl_fk_kernel<<<blocks, 128, smem>>>(in4, out4, nb);
}